// round 10
// baseline (speedup 1.0000x reference)
#include <cuda_runtime.h>
#include <cstdint>

#define M_GT 128
#define M_CHUNK 32
#define N_MCHUNK 4
#define TPB 256
#define A_PER 2
#define TILE (TPB * A_PER)      // 512 anchors per block
#define MAX_NB 512              // anchor-block columns; supports N up to 262144
#define MAX_N 262144

// Scratch (allocation-free: __device__ globals)
__device__ float g_max[N_MCHUNK][MAX_N];            // per-anchor max iou per gt-chunk
__device__ unsigned long long g_part[M_GT][MAX_NB]; // per-(gt, anchor-block) packed best
__device__ unsigned g_forced[M_GT];                 // winning anchor idx per gt
__device__ unsigned char g_flag[MAX_N];             // forced-anchor flags
__device__ unsigned g_list[MAX_N];                  // positive anchor list
__device__ unsigned g_count;                        // positive count

// Correctly-rounded fp32 division for normal operands (Markstein fast path, no guard).
// Bit-identical to div.rn for our operand ranges (verified: rel_err constant across rounds).
__device__ __forceinline__ float exact_div(float num, float den) {
    float r0; asm("rcp.approx.f32 %0, %1;" : "=f"(r0) : "f"(den));
    float e  = __fmaf_rn(-den, r0, 1.0f);
    float r1 = __fmaf_rn(r0, e, r0);
    float y  = __fmul_rn(num, r1);
    float rr = __fmaf_rn(-den, y, num);
    return __fmaf_rn(rr, r1, y);
}

// ---------- Kernel Z: reset flags + counter ----------
__global__ void zero_kernel(int Nw) {   // Nw = words of flags to clear
    int i = blockIdx.x * blockDim.x + threadIdx.x;
    for (; i < Nw; i += gridDim.x * blockDim.x)
        reinterpret_cast<unsigned*>(g_flag)[i] = 0u;
    if (blockIdx.x == 0 && threadIdx.x == 0) g_count = 0u;
}

// ---------- Kernel B: 2D grid: x = anchor tile (512), y = gt chunk (32) ----------
__global__ __launch_bounds__(TPB) void iou_kernel(const float4* __restrict__ anchors,
                                                  const float4* __restrict__ gtb,
                                                  int N) {
    __shared__ float4 s_gt[M_CHUNK];
    __shared__ float  s_area[M_CHUNK];
    __shared__ unsigned long long s_best[M_CHUNK];

    const int t = threadIdx.x;
    const int mbase = blockIdx.y * M_CHUNK;
    if (t < M_CHUNK) {
        float4 g = gtb[mbase + t];
        s_gt[t] = g;
        s_area[t] = (g.z - g.x) * (g.w - g.y);
        s_best[t] = 0x00000000FFFFFFFFull;   // iou=0, idx = ~0xFFFFFFFF = 0 (all-zero column)
    }
    __syncthreads();

    const int lane = t & 31;
    const int base = blockIdx.x * TILE;

    float4   a[A_PER];
    float    area_a[A_PER];
    unsigned aidx[A_PER];
    #pragma unroll
    for (int k = 0; k < A_PER; k++) {
        int i = base + t + k * TPB;        // k=0 has the smaller index
        aidx[k] = (unsigned)i;
        // invalid lanes: degenerate far-away anchor -> iou computes to exactly 0
        float4 av = (i < N) ? anchors[i] : make_float4(3e8f, 3e8f, 3e8f, 3e8f);
        a[k] = av;
        area_a[k] = (av.z - av.x) * (av.w - av.y);
    }

    float best_iou[A_PER] = {0.0f, 0.0f};  // row max only (argmax recovered in pass 2)

    #pragma unroll 8
    for (int m = 0; m < M_CHUNK; m++) {
        const float4 g  = s_gt[m];
        const float  ab = s_area[m];

        unsigned bbits[A_PER];
        #pragma unroll
        for (int k = 0; k < A_PER; k++) {
            float lx = fmaxf(a[k].x, g.x);
            float ly = fmaxf(a[k].y, g.y);
            float rx = fminf(a[k].z, g.z);
            float ry = fminf(a[k].w, g.w);
            float w = fmaxf(rx - lx, 0.0f);
            float h = fmaxf(ry - ly, 0.0f);
            float inter = w * h;
            float uni = (area_a[k] + ab) - inter;    // same association as reference
            float iou = exact_div(inter, uni);       // == div.rn

            best_iou[k] = fmaxf(best_iou[k], iou);   // value only: 1 FMNMX
            bbits[k] = __float_as_uint(iou);         // iou >= 0 -> bits monotonic
        }

        // lane-local best for column argmax (bits tie -> k=0 = smaller index)
        unsigned lbits = umax(bbits[0], bbits[1]);
        unsigned lidx  = (lbits == bbits[0]) ? aidx[0] : aidx[1];

        // per-gt argmax across the warp's 64 anchors (amortized once per warp per gt)
        unsigned wmax = __reduce_max_sync(0xFFFFFFFFu, lbits);
        if (wmax != 0u) {
            unsigned cand = (lbits == wmax) ? lidx : 0xFFFFFFFFu;
            unsigned widx = __reduce_min_sync(0xFFFFFFFFu, cand);   // first index on tie
            if (lane == 0) {
                atomicMax(&s_best[m],
                          ((unsigned long long)wmax << 32) | (unsigned long long)(~widx));
            }
        }
    }

    const int by = blockIdx.y;
    #pragma unroll
    for (int k = 0; k < A_PER; k++) {
        if ((int)aidx[k] < N) g_max[by][aidx[k]] = best_iou[k];
    }

    __syncthreads();
    if (t < M_CHUNK) g_part[mbase + t][blockIdx.x] = s_best[t];
}

// ---------- Kernel R: reduce per-block winners -> forced anchor per gt + scatter flags ----------
__global__ void reduce_kernel(int NB) {
    const int m = blockIdx.x;        // 128 blocks x 32 threads
    const int lane = threadIdx.x;
    unsigned long long best = 0x00000000FFFFFFFFull;
    for (int b = lane; b < NB; b += 32) {
        unsigned long long v = g_part[m][b];
        if (v > best) best = v;
    }
    #pragma unroll
    for (int o = 16; o > 0; o >>= 1) {
        unsigned long long v = __shfl_down_sync(0xFFFFFFFFu, best, o);
        if (v > best) best = v;
    }
    if (lane == 0) {
        unsigned idx = ~(unsigned)(best & 0xFFFFFFFFull);
        g_forced[m] = idx;
        g_flag[idx] = 1;             // scatter: replaces 128-compare loop per anchor
    }
}

// ---------- Kernel C: merge chunk maxima, classify, emit non-pos, collect pos ----------
#define TPB_OUT 256
__global__ __launch_bounds__(TPB_OUT) void out_kernel(float* __restrict__ out, int N) {
    const int i = blockIdx.x * TPB_OUT + threadIdx.x;
    if (i >= N) return;

    float maxiou = fmaxf(fmaxf(g_max[0][i], g_max[1][i]),
                         fmaxf(g_max[2][i], g_max[3][i]));
    bool forced = (g_flag[i] != 0);
    bool pos = (maxiou >= 0.5f) || forced;

    out[5 * N + i] = pos ? 1.0f : 0.0f;
    if (pos) {
        unsigned slot = atomicAdd(&g_count, 1u);
        g_list[slot] = (unsigned)i;          // pass 2 writes cls + reg for these
    } else {
        bool neg = (maxiou < 0.4f);          // !pos already known
        out[i] = neg ? 0.0f : -1.0f;
        reinterpret_cast<float4*>(out + N)[i] = make_float4(0.f, 0.f, 0.f, 0.f);
    }
}

// ---------- Kernel P: per positive anchor, recover argmax j exactly, write cls + encode ----------
#define TPB_POS 256
__global__ __launch_bounds__(TPB_POS) void pos_kernel(const float4* __restrict__ anchors,
                                                      const float4* __restrict__ gtb,
                                                      const int* __restrict__ labels,
                                                      float* __restrict__ out, int N) {
    __shared__ float4 s_gt[M_GT];
    __shared__ float  s_area[M_GT];
    __shared__ int    s_lab[M_GT];

    const int t = threadIdx.x;
    if (t < M_GT) {
        float4 g = gtb[t];
        s_gt[t] = g;
        s_area[t] = (g.z - g.x) * (g.w - g.y);
        s_lab[t] = labels[t];
    }
    __syncthreads();

    const int lane = t & 31;
    const int warps_total = (gridDim.x * TPB_POS) >> 5;
    const int wglobal = (blockIdx.x * TPB_POS + t) >> 5;
    const unsigned count = g_count;

    for (unsigned idx = wglobal; idx < count; idx += warps_total) {
        const int i = (int)g_list[idx];
        float4 a = anchors[i];
        float area_a = (a.z - a.x) * (a.w - a.y);

        // lane handles m = lane, lane+32, lane+64, lane+96 (ascending: first-max kept)
        unsigned bestbits = 0u;
        int      bestm    = lane;
        #pragma unroll
        for (int mm = 0; mm < 4; mm++) {
            int m = mm * 32 + lane;
            float4 g = s_gt[m];
            float lx = fmaxf(a.x, g.x);
            float ly = fmaxf(a.y, g.y);
            float rx = fminf(a.z, g.z);
            float ry = fminf(a.w, g.w);
            float w = fmaxf(rx - lx, 0.0f);
            float h = fmaxf(ry - ly, 0.0f);
            float inter = w * h;
            float uni = (area_a + s_area[m]) - inter;
            float iou = exact_div(inter, uni);       // identical arithmetic to pass 1
            unsigned b = __float_as_uint(iou);
            if (b > bestbits) { bestbits = b; bestm = m; }  // strict > = first-max
        }
        unsigned wmax = __reduce_max_sync(0xFFFFFFFFu, bestbits);
        unsigned cand = (bestbits == wmax) ? (unsigned)bestm : 0xFFFFFFFFu;
        int j = (int)__reduce_min_sync(0xFFFFFFFFu, cand);  // smallest m on tie

        if (lane == 0) {
            float4 g = s_gt[j];
            const float eps = 1.19209290e-07f;  // FLT_EPSILON == jnp.finfo(float32).eps
            float ax = (a.x + a.z) * 0.5f;
            float ay = (a.y + a.w) * 0.5f;
            float aw = fmaxf(a.z - a.x, eps);
            float ah = fmaxf(a.w - a.y, eps);
            float gx = (g.x + g.z) * 0.5f;
            float gy = (g.y + g.w) * 0.5f;
            float gw = g.z - g.x;
            float gh = g.w - g.y;
            float dx = (gx - ax) / aw;
            float dy = (gy - ay) / ah;
            float dw = logf(gw / aw);
            float dh = logf(gh / ah);
            out[i] = (float)s_lab[j];
            reinterpret_cast<float4*>(out + N)[i] = make_float4(dx, dy, dw, dh);
        }
    }
}

extern "C" void kernel_launch(void* const* d_in, const int* in_sizes, int n_in,
                              void* d_out, int out_size) {
    const float4* anchors = (const float4*)d_in[0];
    const float4* gtb     = (const float4*)d_in[1];
    const int*    labels  = (const int*)d_in[2];
    float* out = (float*)d_out;
    const int N = in_sizes[0] / 4;
    const int NBx = (N + TILE - 1) / TILE;

    zero_kernel<<<64, 256>>>((N + 3) / 4);
    dim3 grid(NBx, N_MCHUNK);
    iou_kernel<<<grid, TPB>>>(anchors, gtb, N);
    reduce_kernel<<<M_GT, 32>>>(NBx);
    out_kernel<<<(N + TPB_OUT - 1) / TPB_OUT, TPB_OUT>>>(out, N);
    pos_kernel<<<148, TPB_POS>>>(anchors, gtb, labels, out, N);
}

// round 12
// speedup vs baseline: 1.0184x; 1.0184x over previous
#include <cuda_runtime.h>
#include <cstdint>

#define M_GT 128
#define M_CHUNK 8
#define N_MCHUNK 16
#define TPB 256
#define A_PER 2
#define TILE (TPB * A_PER)      // 512 anchors per block
#define MAX_NB 512              // anchor-block columns; supports N up to 262144
#define MAX_N 262144

// Scratch (allocation-free: __device__ globals)
__device__ unsigned g_max[N_MCHUNK][MAX_N];         // per-anchor max iou BITS per gt-chunk
__device__ unsigned long long g_part[M_GT][MAX_NB]; // per-(gt, anchor-block) packed best
__device__ unsigned char g_flag[MAX_N];             // forced-anchor flags (self-clearing)
__device__ unsigned g_list[MAX_N];                  // positive anchor list
__device__ unsigned g_count;                        // positive count (reset by reduce_kernel)

// Correctly-rounded fp32 division for normal operands (Markstein fast path, no guard).
// Bit-identical to div.rn for our operand ranges (verified: rel_err constant across rounds).
__device__ __forceinline__ float exact_div(float num, float den) {
    float r0; asm("rcp.approx.f32 %0, %1;" : "=f"(r0) : "f"(den));
    float e  = __fmaf_rn(-den, r0, 1.0f);
    float r1 = __fmaf_rn(r0, e, r0);
    float y  = __fmul_rn(num, r1);
    float rr = __fmaf_rn(-den, y, num);
    return __fmaf_rn(rr, r1, y);
}

// ---------- Kernel B: 2D grid: x = anchor tile (512), y = gt chunk (8) ----------
// Inner loop is branch-free, REDUX-free, atomic-free: per-gt argmax kept thread-local
// in registers (bits_m/kk), reduced once per warp AFTER the m-loop.
__global__ __launch_bounds__(TPB) void iou_kernel(const float4* __restrict__ anchors,
                                                  const float4* __restrict__ gtb,
                                                  int N) {
    __shared__ float4 s_gt[M_CHUNK];
    __shared__ float  s_area[M_CHUNK];
    __shared__ unsigned long long s_best[M_CHUNK];

    const int t = threadIdx.x;
    const int mbase = blockIdx.y * M_CHUNK;
    if (t < M_CHUNK) {
        float4 g = gtb[mbase + t];
        s_gt[t] = g;
        s_area[t] = (g.z - g.x) * (g.w - g.y);
        s_best[t] = 0x00000000FFFFFFFFull;   // iou=0, idx = ~0xFFFFFFFF = 0 (all-zero column)
    }
    __syncthreads();

    const int lane = t & 31;
    const int base = blockIdx.x * TILE;

    float4 a[A_PER];
    float  area_a[A_PER];
    #pragma unroll
    for (int k = 0; k < A_PER; k++) {
        int i = base + t + k * TPB;        // k=0 has the smaller anchor index
        // OOB: degenerate far-away anchor -> iou computes to exactly 0 (maskless)
        float4 av = (i < N) ? anchors[i] : make_float4(3e8f, 3e8f, 3e8f, 3e8f);
        a[k] = av;
        area_a[k] = (av.z - av.x) * (av.w - av.y);
    }

    unsigned rowbits[A_PER] = {0u, 0u};    // per-anchor max iou bits
    unsigned bits_m[M_CHUNK];              // thread-local per-gt best bits
    int      kk[M_CHUNK];                  // which k achieved it
    #pragma unroll
    for (int m = 0; m < M_CHUNK; m++) { bits_m[m] = 0u; kk[m] = 0; }

    #pragma unroll
    for (int m = 0; m < M_CHUNK; m++) {
        const float4 g  = s_gt[m];
        const float  ab = s_area[m];
        #pragma unroll
        for (int k = 0; k < A_PER; k++) {
            float lx = fmaxf(a[k].x, g.x);
            float ly = fmaxf(a[k].y, g.y);
            float rx = fminf(a[k].z, g.z);
            float ry = fminf(a[k].w, g.w);
            float w = fmaxf(rx - lx, 0.0f);
            float h = fmaxf(ry - ly, 0.0f);
            float inter = w * h;
            float uni = (area_a[k] + ab) - inter;    // same association as reference
            float iou = exact_div(inter, uni);       // == div.rn
            unsigned b = __float_as_uint(iou);       // iou >= 0 -> bits monotone

            rowbits[k] = umax(rowbits[k], b);
            if (b > bits_m[m]) { bits_m[m] = b; kk[m] = k; }  // strict > keeps smaller k (index)
        }
    }

    const int by = blockIdx.y;
    #pragma unroll
    for (int k = 0; k < A_PER; k++) {
        int i = base + t + k * TPB;
        if (i < N) g_max[by][i] = rowbits[k];
    }

    // Deferred per-gt column argmax: once per warp per gt (8 total).
    #pragma unroll
    for (int m = 0; m < M_CHUNK; m++) {
        unsigned lbits = bits_m[m];
        unsigned lidx  = (unsigned)(base + t + kk[m] * TPB);
        unsigned wmax = __reduce_max_sync(0xFFFFFFFFu, lbits);
        if (wmax != 0u) {   // lbits>0 implies a valid (in-range) anchor
            unsigned cand = (lbits == wmax) ? lidx : 0xFFFFFFFFu;
            unsigned widx = __reduce_min_sync(0xFFFFFFFFu, cand);   // first index on tie
            if (lane == 0) {
                atomicMax(&s_best[m],
                          ((unsigned long long)wmax << 32) | (unsigned long long)(~widx));
            }
        }
    }

    __syncthreads();
    if (t < M_CHUNK) g_part[mbase + t][blockIdx.x] = s_best[t];
}

// ---------- Kernel R: per-gt winner across blocks -> scatter flags; reset pos counter ----------
__global__ void reduce_kernel(int NB) {
    const int m = blockIdx.x;        // 128 blocks x 32 threads
    const int lane = threadIdx.x;
    unsigned long long best = 0x00000000FFFFFFFFull;
    for (int b = lane; b < NB; b += 32) {
        unsigned long long v = g_part[m][b];
        if (v > best) best = v;
    }
    #pragma unroll
    for (int o = 16; o > 0; o >>= 1) {
        unsigned long long v = __shfl_down_sync(0xFFFFFFFFu, best, o);
        if (v > best) best = v;
    }
    if (lane == 0) {
        unsigned idx = ~(unsigned)(best & 0xFFFFFFFFull);
        g_flag[idx] = 1;                       // cleared by out_kernel after reading
        if (m == 0) g_count = 0u;              // reset pos counter for this replay
    }
}

// ---------- Kernel C: merge chunk maxima, classify, emit non-pos, collect pos ----------
#define TPB_OUT 256
__global__ __launch_bounds__(TPB_OUT) void out_kernel(float* __restrict__ out, int N) {
    const int i = blockIdx.x * TPB_OUT + threadIdx.x;
    if (i >= N) return;

    unsigned mb = 0u;
    #pragma unroll
    for (int c = 0; c < N_MCHUNK; c++) mb = umax(mb, g_max[c][i]);
    float maxiou = __uint_as_float(mb);

    bool forced = (g_flag[i] != 0);
    g_flag[i] = 0;                             // self-clear for next graph replay
    bool pos = (maxiou >= 0.5f) || forced;

    out[5 * N + i] = pos ? 1.0f : 0.0f;
    if (pos) {
        unsigned slot = atomicAdd(&g_count, 1u);
        g_list[slot] = (unsigned)i;            // pass 2 writes cls + reg for these
    } else {
        out[i] = (maxiou < 0.4f) ? 0.0f : -1.0f;
        reinterpret_cast<float4*>(out + N)[i] = make_float4(0.f, 0.f, 0.f, 0.f);
    }
}

// ---------- Kernel P: per positive anchor, recover argmax j exactly, write cls + encode ----------
#define TPB_POS 256
__global__ __launch_bounds__(TPB_POS) void pos_kernel(const float4* __restrict__ anchors,
                                                      const float4* __restrict__ gtb,
                                                      const int* __restrict__ labels,
                                                      float* __restrict__ out, int N) {
    __shared__ float4 s_gt[M_GT];
    __shared__ float  s_area[M_GT];
    __shared__ int    s_lab[M_GT];

    const int t = threadIdx.x;
    if (t < M_GT) {
        float4 g = gtb[t];
        s_gt[t] = g;
        s_area[t] = (g.z - g.x) * (g.w - g.y);
        s_lab[t] = labels[t];
    }
    __syncthreads();

    const int lane = t & 31;
    const int warps_total = (gridDim.x * TPB_POS) >> 5;
    const int wglobal = (blockIdx.x * TPB_POS + t) >> 5;
    const unsigned count = g_count;

    for (unsigned idx = wglobal; idx < count; idx += warps_total) {
        const int i = (int)g_list[idx];
        float4 a = anchors[i];
        float area_a = (a.z - a.x) * (a.w - a.y);

        // lane handles m = lane, lane+32, lane+64, lane+96 (ascending: first-max kept)
        unsigned bestbits = 0u;
        int      bestm    = lane;
        #pragma unroll
        for (int mm = 0; mm < 4; mm++) {
            int m = mm * 32 + lane;
            float4 g = s_gt[m];
            float lx = fmaxf(a.x, g.x);
            float ly = fmaxf(a.y, g.y);
            float rx = fminf(a.z, g.z);
            float ry = fminf(a.w, g.w);
            float w = fmaxf(rx - lx, 0.0f);
            float h = fmaxf(ry - ly, 0.0f);
            float inter = w * h;
            float uni = (area_a + s_area[m]) - inter;
            float iou = exact_div(inter, uni);       // identical arithmetic to pass 1
            unsigned b = __float_as_uint(iou);
            if (b > bestbits) { bestbits = b; bestm = m; }  // strict > = first-max
        }
        unsigned wmax = __reduce_max_sync(0xFFFFFFFFu, bestbits);
        unsigned cand = (bestbits == wmax) ? (unsigned)bestm : 0xFFFFFFFFu;
        int j = (int)__reduce_min_sync(0xFFFFFFFFu, cand);  // smallest m on tie

        if (lane == 0) {
            float4 g = s_gt[j];
            const float eps = 1.19209290e-07f;  // FLT_EPSILON == jnp.finfo(float32).eps
            float ax = (a.x + a.z) * 0.5f;
            float ay = (a.y + a.w) * 0.5f;
            float aw = fmaxf(a.z - a.x, eps);
            float ah = fmaxf(a.w - a.y, eps);
            float gx = (g.x + g.z) * 0.5f;
            float gy = (g.y + g.w) * 0.5f;
            float gw = g.z - g.x;
            float gh = g.w - g.y;
            float dx = (gx - ax) / aw;
            float dy = (gy - ay) / ah;
            float dw = logf(gw / aw);
            float dh = logf(gh / ah);
            out[i] = (float)s_lab[j];
            reinterpret_cast<float4*>(out + N)[i] = make_float4(dx, dy, dw, dh);
        }
    }
}

extern "C" void kernel_launch(void* const* d_in, const int* in_sizes, int n_in,
                              void* d_out, int out_size) {
    const float4* anchors = (const float4*)d_in[0];
    const float4* gtb     = (const float4*)d_in[1];
    const int*    labels  = (const int*)d_in[2];
    float* out = (float*)d_out;
    const int N = in_sizes[0] / 4;
    const int NBx = (N + TILE - 1) / TILE;

    dim3 grid(NBx, N_MCHUNK);
    iou_kernel<<<grid, TPB>>>(anchors, gtb, N);
    reduce_kernel<<<M_GT, 32>>>(NBx);
    out_kernel<<<(N + TPB_OUT - 1) / TPB_OUT, TPB_OUT>>>(out, N);
    pos_kernel<<<148, TPB_POS>>>(anchors, gtb, labels, out, N);
}

// round 14
// speedup vs baseline: 1.8082x; 1.7755x over previous
#include <cuda_runtime.h>
#include <cstdint>

#define M_GT 128
#define M_CHUNK 8
#define N_MCHUNK 16
#define TPB 256
#define A_PER 2
#define TILE (TPB * A_PER)      // 512 anchors per block
#define MAX_NB 512              // anchor-block columns; supports N up to 262144
#define MAX_N 262144

// Scratch (allocation-free: __device__ globals)
__device__ unsigned g_bits[N_MCHUNK][MAX_N];        // per-anchor max iou BITS per gt-chunk
__device__ unsigned char g_j[N_MCHUNK][MAX_N];      // per-anchor local argmax (0..7) per chunk
__device__ unsigned long long g_part[M_GT][MAX_NB]; // per-(gt, anchor-block) packed best
__device__ unsigned char g_flag[MAX_N];             // forced-anchor flags (self-clearing)

// Correctly-rounded fp32 division for normal operands (Markstein fast path, no guard).
// Bit-identical to div.rn for our operand ranges (verified: rel_err constant across rounds).
__device__ __forceinline__ float exact_div(float num, float den) {
    float r0; asm("rcp.approx.f32 %0, %1;" : "=f"(r0) : "f"(den));
    float e  = __fmaf_rn(-den, r0, 1.0f);
    float r1 = __fmaf_rn(r0, e, r0);
    float y  = __fmul_rn(num, r1);
    float rr = __fmaf_rn(-den, y, num);
    return __fmaf_rn(rr, r1, y);
}

// ---------- Kernel B: 2D grid: x = anchor tile (512), y = gt chunk (8) ----------
// Inner loop branch-free / REDUX-free / atomic-free. Row max+argmax and per-gt
// column best all live in registers; warp reductions happen once AFTER the loop.
__global__ __launch_bounds__(TPB) void iou_kernel(const float4* __restrict__ anchors,
                                                  const float4* __restrict__ gtb,
                                                  int N) {
    __shared__ float4 s_gt[M_CHUNK];
    __shared__ float  s_area[M_CHUNK];
    __shared__ unsigned long long s_best[M_CHUNK];

    const int t = threadIdx.x;
    const int mbase = blockIdx.y * M_CHUNK;
    if (t < M_CHUNK) {
        float4 g = gtb[mbase + t];
        s_gt[t] = g;
        s_area[t] = (g.z - g.x) * (g.w - g.y);
        s_best[t] = 0x00000000FFFFFFFFull;   // iou=0, idx = ~0xFFFFFFFF = 0 (all-zero column)
    }
    __syncthreads();

    const int lane = t & 31;
    const int base = blockIdx.x * TILE;

    float4 a[A_PER];
    float  area_a[A_PER];
    #pragma unroll
    for (int k = 0; k < A_PER; k++) {
        int i = base + t + k * TPB;        // k=0 has the smaller anchor index
        // OOB: degenerate far-away anchor -> iou computes to exactly 0 (maskless)
        float4 av = (i < N) ? anchors[i] : make_float4(3e8f, 3e8f, 3e8f, 3e8f);
        a[k] = av;
        area_a[k] = (av.z - av.x) * (av.w - av.y);
    }

    unsigned rowbits[A_PER] = {0u, 0u};    // per-anchor max iou bits
    int      rowm[A_PER]    = {0, 0};      // per-anchor local argmax (strict > = first-max)
    unsigned bits_m[M_CHUNK];              // thread-local per-gt best bits
    int      kk[M_CHUNK];                  // which k achieved it
    #pragma unroll
    for (int m = 0; m < M_CHUNK; m++) { bits_m[m] = 0u; kk[m] = 0; }

    #pragma unroll
    for (int m = 0; m < M_CHUNK; m++) {
        const float4 g  = s_gt[m];
        const float  ab = s_area[m];
        #pragma unroll
        for (int k = 0; k < A_PER; k++) {
            float lx = fmaxf(a[k].x, g.x);
            float ly = fmaxf(a[k].y, g.y);
            float rx = fminf(a[k].z, g.z);
            float ry = fminf(a[k].w, g.w);
            float w = fmaxf(rx - lx, 0.0f);
            float h = fmaxf(ry - ly, 0.0f);
            float inter = w * h;
            float uni = (area_a[k] + ab) - inter;    // same association as reference
            float iou = exact_div(inter, uni);       // == div.rn
            unsigned b = __float_as_uint(iou);       // iou >= 0 -> bits monotone

            if (b > rowbits[k]) { rowbits[k] = b; rowm[k] = m; }   // strict > = first-max (rows)
            if (b > bits_m[m])  { bits_m[m] = b; kk[m] = k; }      // strict > keeps smaller k
        }
    }

    const int by = blockIdx.y;
    #pragma unroll
    for (int k = 0; k < A_PER; k++) {
        int i = base + t + k * TPB;
        if (i < N) {
            g_bits[by][i] = rowbits[k];
            g_j[by][i]    = (unsigned char)rowm[k];
        }
    }

    // Deferred per-gt column argmax: once per warp per gt (8 total).
    #pragma unroll
    for (int m = 0; m < M_CHUNK; m++) {
        unsigned lbits = bits_m[m];
        unsigned lidx  = (unsigned)(base + t + kk[m] * TPB);
        unsigned wmax = __reduce_max_sync(0xFFFFFFFFu, lbits);
        if (wmax != 0u) {   // lbits>0 implies a valid (in-range) anchor
            unsigned cand = (lbits == wmax) ? lidx : 0xFFFFFFFFu;
            unsigned widx = __reduce_min_sync(0xFFFFFFFFu, cand);   // first index on tie
            if (lane == 0) {
                atomicMax(&s_best[m],
                          ((unsigned long long)wmax << 32) | (unsigned long long)(~widx));
            }
        }
    }

    __syncthreads();
    if (t < M_CHUNK) g_part[mbase + t][blockIdx.x] = s_best[t];
}

// ---------- Kernel R: per-gt winner across blocks -> scatter forced flags ----------
__global__ void reduce_kernel(int NB) {
    const int m = blockIdx.x;        // 128 blocks x 32 threads
    const int lane = threadIdx.x;
    unsigned long long best = 0x00000000FFFFFFFFull;
    for (int b = lane; b < NB; b += 32) {
        unsigned long long v = g_part[m][b];
        if (v > best) best = v;
    }
    #pragma unroll
    for (int o = 16; o > 0; o >>= 1) {
        unsigned long long v = __shfl_down_sync(0xFFFFFFFFu, best, o);
        if (v > best) best = v;
    }
    if (lane == 0) {
        unsigned idx = ~(unsigned)(best & 0xFFFFFFFFull);
        g_flag[idx] = 1;             // read + cleared by out_kernel (graph-replay safe)
    }
}

// ---------- Kernel C: merge chunks, classify, label + encode, write all outputs ----------
#define TPB_OUT 256
__global__ __launch_bounds__(TPB_OUT) void out_kernel(const float4* __restrict__ anchors,
                                                      const float4* __restrict__ gtb,
                                                      const int* __restrict__ labels,
                                                      float* __restrict__ out, int N) {
    __shared__ float4 s_gt[M_GT];
    __shared__ int    s_lab[M_GT];

    const int t = threadIdx.x;
    if (t < M_GT) {
        s_gt[t]  = gtb[t];
        s_lab[t] = labels[t];
    }
    __syncthreads();

    const int i = blockIdx.x * TPB_OUT + t;
    if (i >= N) return;

    // merge 16 gt-chunks: strict > in ascending chunk order = global first-max
    unsigned mb = g_bits[0][i];
    int j = (int)g_j[0][i];
    #pragma unroll
    for (int c = 1; c < N_MCHUNK; c++) {
        unsigned b = g_bits[c][i];
        int jj = (int)g_j[c][i] + c * M_CHUNK;
        if (b > mb) { mb = b; j = jj; }
    }
    float maxiou = __uint_as_float(mb);

    bool forced = (g_flag[i] != 0);
    g_flag[i] = 0;                             // self-clear for next graph replay
    bool pos = (maxiou >= 0.5f) || forced;
    bool neg = (maxiou < 0.4f) && !pos;
    int  cls = pos ? s_lab[j] : (neg ? 0 : -1);

    float4 a = anchors[i];
    float4 g = s_gt[j];

    const float eps = 1.19209290e-07f;  // FLT_EPSILON == jnp.finfo(float32).eps
    float ax = (a.x + a.z) * 0.5f;
    float ay = (a.y + a.w) * 0.5f;
    float aw = fmaxf(a.z - a.x, eps);
    float ah = fmaxf(a.w - a.y, eps);
    float gx = (g.x + g.z) * 0.5f;
    float gy = (g.y + g.w) * 0.5f;
    float gw = g.z - g.x;
    float gh = g.w - g.y;

    float dx = (gx - ax) / aw;
    float dy = (gy - ay) / ah;
    float dw = logf(gw / aw);
    float dh = logf(gh / ah);

    // output layout (float32): [cls (N)] [reg (N,4)] [pos (N)]
    out[i] = (float)cls;
    float4 r = pos ? make_float4(dx, dy, dw, dh) : make_float4(0.f, 0.f, 0.f, 0.f);
    reinterpret_cast<float4*>(out + N)[i] = r;   // out+N is 16B-aligned (N multiple of 4)
    out[5 * N + i] = pos ? 1.0f : 0.0f;
}

extern "C" void kernel_launch(void* const* d_in, const int* in_sizes, int n_in,
                              void* d_out, int out_size) {
    const float4* anchors = (const float4*)d_in[0];
    const float4* gtb     = (const float4*)d_in[1];
    const int*    labels  = (const int*)d_in[2];
    float* out = (float*)d_out;
    const int N = in_sizes[0] / 4;
    const int NBx = (N + TILE - 1) / TILE;

    dim3 grid(NBx, N_MCHUNK);
    iou_kernel<<<grid, TPB>>>(anchors, gtb, N);
    reduce_kernel<<<M_GT, 32>>>(NBx);
    out_kernel<<<(N + TPB_OUT - 1) / TPB_OUT, TPB_OUT>>>(anchors, gtb, labels, out, N);
}